// round 5
// baseline (speedup 1.0000x reference)
#include <cuda_runtime.h>
#include <cuda_bf16.h>
#include <cstdint>

#define DIMV 64
#define WPC  8    // warps per CTA (split-K ways)

// B packed in mma-fragment order under the K-permutation that makes A loads
// float4-contiguous: Bp[(ks*8 + j)*32 + lane] = {b0, b1}
//   b0 = bf16x2{ x[k0+4t][n], x[k0+4t+1][n] }
//   b1 = bf16x2{ x[k0+4t+2][n], x[k0+4t+3][n] },  n = j*8+g
__device__ uint2 g_Bp[640 * 8 * 32];

// ---------------- helpers ----------------
__device__ __forceinline__ uint32_t cvt_bf16x2(float lo, float hi) {
    uint32_t r;
    asm("cvt.rn.bf16x2.f32 %0, %1, %2;" : "=r"(r) : "f"(hi), "f"(lo));
    return r;
}

__device__ __forceinline__ void mma16816(float c[4], const uint32_t a[4],
                                         uint32_t b0, uint32_t b1) {
    asm volatile(
        "mma.sync.aligned.m16n8k16.row.col.f32.bf16.bf16.f32 "
        "{%0,%1,%2,%3}, {%4,%5,%6,%7}, {%8,%9}, {%0,%1,%2,%3};"
        : "+f"(c[0]), "+f"(c[1]), "+f"(c[2]), "+f"(c[3])
        : "r"(a[0]), "r"(a[1]), "r"(a[2]), "r"(a[3]), "r"(b0), "r"(b1));
}

// ---------------- kernel 1: pack x -> Bp (permuted fragment order) ----------
// grid = nk (625), block = 256 (8 j-tiles x 32 lanes)
__global__ void __launch_bounds__(256) pack_kernel(const float* __restrict__ x, int N) {
    __shared__ float xs[16][64];
    int ks = blockIdx.x;
    int k0 = ks * 16;
    for (int i = threadIdx.x; i < 16 * 64; i += 256) {
        int r = i >> 6, c = i & 63;
        xs[r][c] = x[(size_t)(k0 + r) * DIMV + c];
    }
    __syncthreads();
    int j = threadIdx.x >> 5, lane = threadIdx.x & 31;
    int g = lane >> 2, t = lane & 3;
    int n = j * 8 + g;
    // permuted: fragment slot b0 <- actual k = 4t, 4t+1 ; b1 <- 4t+2, 4t+3
    uint32_t lo = cvt_bf16x2(xs[4 * t][n],     xs[4 * t + 1][n]);
    uint32_t hi = cvt_bf16x2(xs[4 * t + 2][n], xs[4 * t + 3][n]);
    g_Bp[(size_t)(ks * 8 + j) * 32 + lane] = make_uint2(lo, hi);
}

// ---------------- kernel 2: fused GEMM + epilogue ----------------
// One CTA = one 16-row tile; 8 warps split K; smem reduce; float4 A loads.
__global__ void __launch_bounds__(WPC * 32, 2)
gemm_kernel(const float* __restrict__ A, const float* __restrict__ x,
            float* __restrict__ out, int N) {
    __shared__ float wred[WPC][16];
    __shared__ float wfin[16];

    int tid = threadIdx.x, w = tid >> 5, lane = tid & 31;
    int g = lane >> 2, t = lane & 3;
    int row0 = blockIdx.x * 16;
    int r0 = row0 + g, r1 = r0 + 8;

    // lane loads A[r][k0 + 4t .. k0 + 4t + 3] as one float4
    const float4* pA0 = (const float4*)(A + (size_t)r0 * N + 4 * t);
    const float4* pA1 = (const float4*)(A + (size_t)r1 * N + 4 * t);

    float c[8][4];
#pragma unroll
    for (int j = 0; j < 8; j++)
#pragma unroll
        for (int q = 0; q < 4; q++) c[j][q] = 0.0f;

    int nk = N >> 4;  // 625 K-steps of 16
#pragma unroll 2
    for (int ks = w; ks < nk; ks += WPC) {
        // A fragment: rows r0, r1 ; 16 actual k each, one LDG.128 per row
        float4 va = pA0[ks << 2];
        float4 vb = pA1[ks << 2];

        const uint2* bp = g_Bp + (size_t)ks * 256 + lane;
        uint2 bb[8];
#pragma unroll
        for (int j = 0; j < 8; j++) bb[j] = bp[(size_t)j * 32];

        uint32_t ar[4];
        ar[0] = cvt_bf16x2(va.x, va.y);   // slot a0: row g,  logical k 2t,2t+1
        ar[1] = cvt_bf16x2(vb.x, vb.y);   // slot a1: row g+8
        ar[2] = cvt_bf16x2(va.z, va.w);   // slot a2: row g,  logical k 2t+8,2t+9
        ar[3] = cvt_bf16x2(vb.z, vb.w);   // slot a3: row g+8

#pragma unroll
        for (int j = 0; j < 8; j++)
            mma16816(c[j], ar, bb[j].x, bb[j].y);
    }

    // per-warp partial dot of x . (Ax)_partial over owned columns
    float s0 = 0.0f, s1 = 0.0f;
#pragma unroll
    for (int j = 0; j < 8; j++) {
        int col = j * 8 + t * 2;
        float2 x0 = *(const float2*)(x + (size_t)r0 * DIMV + col);
        float2 x1 = *(const float2*)(x + (size_t)r1 * DIMV + col);
        s0 += x0.x * c[j][0] + x0.y * c[j][1];
        s1 += x1.x * c[j][2] + x1.y * c[j][3];
    }
    s0 += __shfl_xor_sync(0xFFFFFFFFu, s0, 1);
    s0 += __shfl_xor_sync(0xFFFFFFFFu, s0, 2);
    s1 += __shfl_xor_sync(0xFFFFFFFFu, s1, 1);
    s1 += __shfl_xor_sync(0xFFFFFFFFu, s1, 2);

    if (t == 0) { wred[w][g] = s0; wred[w][g + 8] = s1; }
    __syncthreads();

    if (tid < 16) {
        float acc = 0.0f;
#pragma unroll
        for (int q = 0; q < WPC; q++) acc += wred[q][tid];
        wfin[tid] = 0.01f * acc;
    }
    __syncthreads();

    // write out: 16 rows x 64 cols, coalesced float4 (exactly 1 item/thread)
    {
        int i = tid;
        int r = i >> 4, cq = i & 15;
        const float* xr = x + (size_t)(row0 + r) * DIMV + cq * 4;
        float4 xv = *(const float4*)xr;
        float inter = wfin[r];
        float4 o;
        o.x = 1.0f - 0.1f * xv.x - inter;
        o.y = 1.0f - 0.1f * xv.y - inter;
        o.z = 1.0f - 0.1f * xv.z - inter;
        o.w = 1.0f - 0.1f * xv.w - inter;
        *(float4*)(out + (size_t)(row0 + r) * DIMV + cq * 4) = o;
    }
}

// ---------------- launch ----------------
extern "C" void kernel_launch(void* const* d_in, const int* in_sizes, int n_in,
                              void* d_out, int out_size) {
    const float* x = (const float*)d_in[1];
    const float* A = (const float*)d_in[2];
    float* out = (float*)d_out;
    int N = in_sizes[1] / DIMV;   // 10000
    int nk = N >> 4;              // 625

    pack_kernel<<<nk, 256>>>(x, N);
    gemm_kernel<<<N / 16, WPC * 32>>>(A, x, out, N);
}

// round 6
// speedup vs baseline: 1.0022x; 1.0022x over previous
#include <cuda_runtime.h>
#include <cuda_bf16.h>
#include <cstdint>

#define DIMV 64
#define WPC  8    // warps per CTA (split-K ways)

// B packed as uint4, fragment order under the K-permutation that makes A loads
// float4-contiguous:
//   g_Bp[(ks*4 + jj)*32 + lane] = { lo(j=2jj), hi(2jj), lo(2jj+1), hi(2jj+1) }
//   lo(j) = bf16x2{ x[k0+4t][n], x[k0+4t+1][n] },  hi(j) = same at k0+4t+2/3
//   n = j*8 + g
__device__ uint4 g_Bp[640 * 4 * 32];

// ---------------- helpers ----------------
__device__ __forceinline__ uint32_t cvt_bf16x2(float lo, float hi) {
    uint32_t r;
    asm("cvt.rn.bf16x2.f32 %0, %1, %2;" : "=r"(r) : "f"(hi), "f"(lo));
    return r;
}

__device__ __forceinline__ void mma16816(float c[4], const uint32_t a[4],
                                         uint32_t b0, uint32_t b1) {
    asm volatile(
        "mma.sync.aligned.m16n8k16.row.col.f32.bf16.bf16.f32 "
        "{%0,%1,%2,%3}, {%4,%5,%6,%7}, {%8,%9}, {%0,%1,%2,%3};"
        : "+f"(c[0]), "+f"(c[1]), "+f"(c[2]), "+f"(c[3])
        : "r"(a[0]), "r"(a[1]), "r"(a[2]), "r"(a[3]), "r"(b0), "r"(b1));
}

// ---------------- kernel 1: pack x -> Bp (permuted fragment order, uint4) ----
// grid = nk (625), block = 128 (4 jj-tiles x 32 lanes)
__global__ void __launch_bounds__(128) pack_kernel(const float* __restrict__ x, int N) {
    __shared__ float xs[16][64];
    int ks = blockIdx.x;
    int k0 = ks * 16;
    for (int i = threadIdx.x; i < 16 * 64; i += 128) {
        int r = i >> 6, c = i & 63;
        xs[r][c] = x[(size_t)(k0 + r) * DIMV + c];
    }
    __syncthreads();
    int jj = threadIdx.x >> 5, lane = threadIdx.x & 31;
    int g = lane >> 2, t = lane & 3;
    int n0 = jj * 16 + g;       // j = 2*jj
    int n1 = n0 + 8;            // j = 2*jj + 1
    uint4 v;
    v.x = cvt_bf16x2(xs[4 * t][n0],     xs[4 * t + 1][n0]);
    v.y = cvt_bf16x2(xs[4 * t + 2][n0], xs[4 * t + 3][n0]);
    v.z = cvt_bf16x2(xs[4 * t][n1],     xs[4 * t + 1][n1]);
    v.w = cvt_bf16x2(xs[4 * t + 2][n1], xs[4 * t + 3][n1]);
    g_Bp[(size_t)(ks * 4 + jj) * 32 + lane] = v;
}

// ---------------- kernel 2: fused GEMM + epilogue, SW-pipelined ----------------
__global__ void __launch_bounds__(WPC * 32, 2)
gemm_kernel(const float* __restrict__ A, const float* __restrict__ x,
            float* __restrict__ out, int N) {
    __shared__ float wred[WPC][16];
    __shared__ float wfin[16];

    int tid = threadIdx.x, w = tid >> 5, lane = tid & 31;
    int g = lane >> 2, t = lane & 3;
    int row0 = blockIdx.x * 16;
    int r0 = row0 + g, r1 = r0 + 8;

    const float4* pA0 = (const float4*)(A + (size_t)r0 * N + 4 * t);
    const float4* pA1 = (const float4*)(A + (size_t)r1 * N + 4 * t);
    const uint4*  pB  = g_Bp + lane;

    float c[8][4];
#pragma unroll
    for (int j = 0; j < 8; j++)
#pragma unroll
        for (int q = 0; q < 4; q++) c[j][q] = 0.0f;

    int nk = N >> 4;          // 625
    int last = nk - 1;

    // ---- prologue: A depth-2, B depth-1 prefetch ----
    int ks  = w;
    int ks1 = min(ks + WPC, last);
    float4 a0_0 = pA0[ks  << 2], a1_0 = pA1[ks  << 2];
    float4 a0_1 = pA0[ks1 << 2], a1_1 = pA1[ks1 << 2];
    uint4 bb[4];
#pragma unroll
    for (int jj = 0; jj < 4; jj++) bb[jj] = pB[(size_t)(ks * 4 + jj) * 32];

    for (; ks < nk; ks += WPC) {
        int ksA = ks + 2 * WPC; if (ksA > last) ksA = last;
        int ksB = ks + WPC;     if (ksB > last) ksB = last;

        // issue future loads first
        float4 na0 = pA0[ksA << 2];
        float4 na1 = pA1[ksA << 2];
        uint4 nb[4];
#pragma unroll
        for (int jj = 0; jj < 4; jj++) nb[jj] = pB[(size_t)(ksB * 4 + jj) * 32];

        // compute current iteration
        uint32_t ar[4];
        ar[0] = cvt_bf16x2(a0_0.x, a0_0.y);
        ar[1] = cvt_bf16x2(a1_0.x, a1_0.y);
        ar[2] = cvt_bf16x2(a0_0.z, a0_0.w);
        ar[3] = cvt_bf16x2(a1_0.z, a1_0.w);

#pragma unroll
        for (int jj = 0; jj < 4; jj++) {
            mma16816(c[2 * jj],     ar, bb[jj].x, bb[jj].y);
            mma16816(c[2 * jj + 1], ar, bb[jj].z, bb[jj].w);
        }

        // rotate pipeline
        a0_0 = a0_1; a1_0 = a1_1;
        a0_1 = na0;  a1_1 = na1;
#pragma unroll
        for (int jj = 0; jj < 4; jj++) bb[jj] = nb[jj];
    }

    // ---- epilogue: per-warp partial dot x . (Ax)_partial ----
    float s0 = 0.0f, s1 = 0.0f;
#pragma unroll
    for (int j = 0; j < 8; j++) {
        int col = j * 8 + t * 2;
        float2 x0 = *(const float2*)(x + (size_t)r0 * DIMV + col);
        float2 x1 = *(const float2*)(x + (size_t)r1 * DIMV + col);
        s0 += x0.x * c[j][0] + x0.y * c[j][1];
        s1 += x1.x * c[j][2] + x1.y * c[j][3];
    }
    s0 += __shfl_xor_sync(0xFFFFFFFFu, s0, 1);
    s0 += __shfl_xor_sync(0xFFFFFFFFu, s0, 2);
    s1 += __shfl_xor_sync(0xFFFFFFFFu, s1, 1);
    s1 += __shfl_xor_sync(0xFFFFFFFFu, s1, 2);

    if (t == 0) { wred[w][g] = s0; wred[w][g + 8] = s1; }
    __syncthreads();

    if (tid < 16) {
        float acc = 0.0f;
#pragma unroll
        for (int q = 0; q < WPC; q++) acc += wred[q][tid];
        wfin[tid] = 0.01f * acc;
    }
    __syncthreads();

    // write out: 16 rows x 64 cols, one float4 per thread
    {
        int r = tid >> 4, cq = tid & 15;
        const float* xr = x + (size_t)(row0 + r) * DIMV + cq * 4;
        float4 xv = *(const float4*)xr;
        float inter = wfin[r];
        float4 o;
        o.x = 1.0f - 0.1f * xv.x - inter;
        o.y = 1.0f - 0.1f * xv.y - inter;
        o.z = 1.0f - 0.1f * xv.z - inter;
        o.w = 1.0f - 0.1f * xv.w - inter;
        *(float4*)(out + (size_t)(row0 + r) * DIMV + cq * 4) = o;
    }
}

// ---------------- launch ----------------
extern "C" void kernel_launch(void* const* d_in, const int* in_sizes, int n_in,
                              void* d_out, int out_size) {
    const float* x = (const float*)d_in[1];
    const float* A = (const float*)d_in[2];
    float* out = (float*)d_out;
    int N = in_sizes[1] / DIMV;   // 10000
    int nk = N >> 4;              // 625

    pack_kernel<<<nk, 128>>>(x, N);
    gemm_kernel<<<N / 16, WPC * 32>>>(A, x, out, N);
}

// round 7
// speedup vs baseline: 1.0388x; 1.0365x over previous
#include <cuda_runtime.h>
#include <cuda_bf16.h>
#include <cstdint>

#define DIMV  64
#define WPC   8     // warps per CTA (split-K ways)
#define DEPTH 5     // cp.async ring depth (K-steps in flight per warp)

// B packed as uint4, fragment order under the K-permutation that makes A loads
// float4-contiguous (see pack_kernel).
__device__ uint4 g_Bp[640 * 4 * 32];

// ---------------- helpers ----------------
__device__ __forceinline__ uint32_t cvt_bf16x2(float lo, float hi) {
    uint32_t r;
    asm("cvt.rn.bf16x2.f32 %0, %1, %2;" : "=r"(r) : "f"(hi), "f"(lo));
    return r;
}

__device__ __forceinline__ uint32_t smem_u32(const void* p) {
    uint32_t a;
    asm("{ .reg .u64 t; cvta.to.shared.u64 t, %1; cvt.u32.u64 %0, t; }" : "=r"(a) : "l"(p));
    return a;
}

__device__ __forceinline__ void cp_async16(uint32_t dst, const void* src) {
    asm volatile("cp.async.cg.shared.global [%0], [%1], 16;"
                 :: "r"(dst), "l"(src) : "memory");
}
#define CP_COMMIT() asm volatile("cp.async.commit_group;" ::: "memory")
#define CP_WAIT()   asm volatile("cp.async.wait_group %0;" :: "n"(DEPTH - 1) : "memory")

__device__ __forceinline__ void lds128(float4& v, uint32_t addr) {
    asm volatile("ld.shared.v4.f32 {%0,%1,%2,%3}, [%4];"
                 : "=f"(v.x), "=f"(v.y), "=f"(v.z), "=f"(v.w) : "r"(addr));
}

__device__ __forceinline__ void mma16816(float c[4], const uint32_t a[4],
                                         uint32_t b0, uint32_t b1) {
    asm volatile(
        "mma.sync.aligned.m16n8k16.row.col.f32.bf16.bf16.f32 "
        "{%0,%1,%2,%3}, {%4,%5,%6,%7}, {%8,%9}, {%0,%1,%2,%3};"
        : "+f"(c[0]), "+f"(c[1]), "+f"(c[2]), "+f"(c[3])
        : "r"(a[0]), "r"(a[1]), "r"(a[2]), "r"(a[3]), "r"(b0), "r"(b1));
}

// ---------------- kernel 1: pack x -> Bp (permuted fragment order, uint4) ----
__global__ void __launch_bounds__(128) pack_kernel(const float* __restrict__ x, int N) {
    __shared__ float xs[16][64];
    int ks = blockIdx.x;
    int k0 = ks * 16;
    for (int i = threadIdx.x; i < 16 * 64; i += 128) {
        int r = i >> 6, c = i & 63;
        xs[r][c] = x[(size_t)(k0 + r) * DIMV + c];
    }
    __syncthreads();
    int jj = threadIdx.x >> 5, lane = threadIdx.x & 31;
    int g = lane >> 2, t = lane & 3;
    int n0 = jj * 16 + g;
    int n1 = n0 + 8;
    uint4 v;
    v.x = cvt_bf16x2(xs[4 * t][n0],     xs[4 * t + 1][n0]);
    v.y = cvt_bf16x2(xs[4 * t + 2][n0], xs[4 * t + 3][n0]);
    v.z = cvt_bf16x2(xs[4 * t][n1],     xs[4 * t + 1][n1]);
    v.w = cvt_bf16x2(xs[4 * t + 2][n1], xs[4 * t + 3][n1]);
    g_Bp[(size_t)(ks * 4 + jj) * 32 + lane] = v;
}

// ---------------- kernel 2: fused GEMM + epilogue, cp.async ring ----------------
__global__ void __launch_bounds__(WPC * 32, 2)
gemm_kernel(const float* __restrict__ A, const float* __restrict__ x,
            float* __restrict__ out, int N) {
    // per-warp ring: [warp][slot][64 float4]  (r0 half: 0..31, r1 half: 32..63)
    __shared__ float4 ring[WPC][DEPTH][64];
    __shared__ float wred[WPC][16];
    __shared__ float wfin[16];

    int tid = threadIdx.x, w = tid >> 5, lane = tid & 31;
    int g = lane >> 2, t = lane & 3;
    int row0 = blockIdx.x * 16;
    int r0 = row0 + g, r1 = r0 + 8;

    // global srcs: lane loads A[r][ks*16 + 4t .. +3]
    const char* gA0 = (const char*)(A + (size_t)r0 * N + 4 * t);
    const char* gA1 = (const char*)(A + (size_t)r1 * N + 4 * t);
    const uint4* pB = g_Bp + lane;

    uint32_t ring0 = smem_u32(&ring[w][0][0]) + lane * 16;  // r0 dst, slot 0
    // slot stride = 64 * 16 = 1024 B; r1 half at +512

    float c[8][4];
#pragma unroll
    for (int j = 0; j < 8; j++)
#pragma unroll
        for (int q = 0; q < 4; q++) c[j][q] = 0.0f;

    int nk = N >> 4;          // 625
    int pf = w;

    // ---- prologue: fill ring ----
#pragma unroll
    for (int d = 0; d < DEPTH; d++) {
        if (pf < nk) {
            uint32_t dst = ring0 + d * 1024;
            cp_async16(dst,       gA0 + (size_t)pf * 64);
            cp_async16(dst + 512, gA1 + (size_t)pf * 64);
        }
        CP_COMMIT();
        pf += WPC;
    }

    int last = nk - 1;
    uint4 bb[4];
    {
        int ks0 = min(w, last);
#pragma unroll
        for (int jj = 0; jj < 4; jj++) bb[jj] = pB[(size_t)(ks0 * 4 + jj) * 32];
    }

    int slot = 0;
    for (int ks = w; ks < nk; ks += WPC) {
        CP_WAIT();   // oldest group (this slot) complete

        // B prefetch for next iteration (L2-resident)
        int ksB = ks + WPC; if (ksB > last) ksB = last;
        uint4 nb[4];
#pragma unroll
        for (int jj = 0; jj < 4; jj++) nb[jj] = pB[(size_t)(ksB * 4 + jj) * 32];

        // consume A from ring (conflict-free: lane reads its own 16 B)
        uint32_t sbase = ring0 + slot * 1024;
        float4 va, vb;
        lds128(va, sbase);
        lds128(vb, sbase + 512);

        uint32_t ar[4];
        ar[0] = cvt_bf16x2(va.x, va.y);
        ar[1] = cvt_bf16x2(vb.x, vb.y);
        ar[2] = cvt_bf16x2(va.z, va.w);
        ar[3] = cvt_bf16x2(vb.z, vb.w);

#pragma unroll
        for (int jj = 0; jj < 4; jj++) {
            mma16816(c[2 * jj],     ar, bb[jj].x, bb[jj].y);
            mma16816(c[2 * jj + 1], ar, bb[jj].z, bb[jj].w);
        }

        // refill this slot with K-step pf
        if (pf < nk) {
            cp_async16(sbase,       gA0 + (size_t)pf * 64);
            cp_async16(sbase + 512, gA1 + (size_t)pf * 64);
        }
        CP_COMMIT();
        pf += WPC;

#pragma unroll
        for (int jj = 0; jj < 4; jj++) bb[jj] = nb[jj];
        slot = (slot + 1 == DEPTH) ? 0 : slot + 1;
    }

    // ---- epilogue: per-warp partial dot x . (Ax)_partial ----
    float s0 = 0.0f, s1 = 0.0f;
#pragma unroll
    for (int j = 0; j < 8; j++) {
        int col = j * 8 + t * 2;
        float2 x0 = *(const float2*)(x + (size_t)r0 * DIMV + col);
        float2 x1 = *(const float2*)(x + (size_t)r1 * DIMV + col);
        s0 += x0.x * c[j][0] + x0.y * c[j][1];
        s1 += x1.x * c[j][2] + x1.y * c[j][3];
    }
    s0 += __shfl_xor_sync(0xFFFFFFFFu, s0, 1);
    s0 += __shfl_xor_sync(0xFFFFFFFFu, s0, 2);
    s1 += __shfl_xor_sync(0xFFFFFFFFu, s1, 1);
    s1 += __shfl_xor_sync(0xFFFFFFFFu, s1, 2);

    if (t == 0) { wred[w][g] = s0; wred[w][g + 8] = s1; }
    __syncthreads();

    if (tid < 16) {
        float acc = 0.0f;
#pragma unroll
        for (int q = 0; q < WPC; q++) acc += wred[q][tid];
        wfin[tid] = 0.01f * acc;
    }
    __syncthreads();

    {
        int r = tid >> 4, cq = tid & 15;
        const float* xr = x + (size_t)(row0 + r) * DIMV + cq * 4;
        float4 xv = *(const float4*)xr;
        float inter = wfin[r];
        float4 o;
        o.x = 1.0f - 0.1f * xv.x - inter;
        o.y = 1.0f - 0.1f * xv.y - inter;
        o.z = 1.0f - 0.1f * xv.z - inter;
        o.w = 1.0f - 0.1f * xv.w - inter;
        *(float4*)(out + (size_t)(row0 + r) * DIMV + cq * 4) = o;
    }
}

// ---------------- launch ----------------
extern "C" void kernel_launch(void* const* d_in, const int* in_sizes, int n_in,
                              void* d_out, int out_size) {
    const float* x = (const float*)d_in[1];
    const float* A = (const float*)d_in[2];
    float* out = (float*)d_out;
    int N = in_sizes[1] / DIMV;   // 10000
    int nk = N >> 4;              // 625

    pack_kernel<<<nk, 128>>>(x, N);
    gemm_kernel<<<N / 16, WPC * 32>>>(A, x, out, N);
}

// round 8
// speedup vs baseline: 1.1074x; 1.0660x over previous
#include <cuda_runtime.h>
#include <cuda_bf16.h>
#include <cstdint>

#define DIMV    64
#define KSPLIT  4
#define STAGES_PER_CTA 10     // 40 padded global stages / KSPLIT
#define RING    4             // smem ring depth
#define ROWSTRIDE 1088        // bytes per row in smem (conflict-free: 1088 % 128 == 64)
#define STAGE_BYTES (16 * ROWSTRIDE)   // 17408

// B packed as uint4, fragment order under the K-permutation that makes A loads
// float4-contiguous. Sized for 640 K-steps; ks >= 625 stays zero (zero-init).
__device__ uint4 g_Bp[640 * 4 * 32];
// per-row interaction scalar accumulator (zeroed each launch via memsetAsync)
__device__ float g_w[10240];

// ---------------- helpers ----------------
__device__ __forceinline__ uint32_t cvt_bf16x2(float lo, float hi) {
    uint32_t r;
    asm("cvt.rn.bf16x2.f32 %0, %1, %2;" : "=r"(r) : "f"(hi), "f"(lo));
    return r;
}
__device__ __forceinline__ uint32_t smem_u32(const void* p) {
    uint32_t a;
    asm("{ .reg .u64 t; cvta.to.shared.u64 t, %1; cvt.u32.u64 %0, t; }" : "=r"(a) : "l"(p));
    return a;
}
__device__ __forceinline__ void cp_async16(uint32_t dst, const void* src) {
    asm volatile("cp.async.cg.shared.global [%0], [%1], 16;"
                 :: "r"(dst), "l"(src) : "memory");
}
#define CP_COMMIT() asm volatile("cp.async.commit_group;" ::: "memory")
#define CP_WAIT2()  asm volatile("cp.async.wait_group %0;" :: "n"(RING - 2) : "memory")

__device__ __forceinline__ void lds128(float4& v, uint32_t addr) {
    asm volatile("ld.shared.v4.f32 {%0,%1,%2,%3}, [%4];"
                 : "=f"(v.x), "=f"(v.y), "=f"(v.z), "=f"(v.w) : "r"(addr));
}
__device__ __forceinline__ void mma16816(float c[4], const uint32_t a[4],
                                         uint32_t b0, uint32_t b1) {
    asm volatile(
        "mma.sync.aligned.m16n8k16.row.col.f32.bf16.bf16.f32 "
        "{%0,%1,%2,%3}, {%4,%5,%6,%7}, {%8,%9}, {%0,%1,%2,%3};"
        : "+f"(c[0]), "+f"(c[1]), "+f"(c[2]), "+f"(c[3])
        : "r"(a[0]), "r"(a[1]), "r"(a[2]), "r"(a[3]), "r"(b0), "r"(b1));
}

// ---------------- kernel 1: pack x -> Bp (permuted fragment order, uint4) ----
__global__ void __launch_bounds__(128) pack_kernel(const float* __restrict__ x, int N) {
    __shared__ float xs[16][64];
    int ks = blockIdx.x;
    int k0 = ks * 16;
    for (int i = threadIdx.x; i < 16 * 64; i += 128) {
        int r = i >> 6, c = i & 63;
        xs[r][c] = x[(size_t)(k0 + r) * DIMV + c];
    }
    __syncthreads();
    int jj = threadIdx.x >> 5, lane = threadIdx.x & 31;
    int g = lane >> 2, t = lane & 3;
    int n0 = jj * 16 + g;
    int n1 = n0 + 8;
    uint4 v;
    v.x = cvt_bf16x2(xs[4 * t][n0],     xs[4 * t + 1][n0]);
    v.y = cvt_bf16x2(xs[4 * t + 2][n0], xs[4 * t + 3][n0]);
    v.z = cvt_bf16x2(xs[4 * t][n1],     xs[4 * t + 1][n1]);
    v.w = cvt_bf16x2(xs[4 * t + 2][n1], xs[4 * t + 3][n1]);
    g_Bp[(size_t)(ks * 4 + jj) * 32 + lane] = v;
}

// ---------------- kernel 2: cooperative-stage GEMM, split-K x4 ----------------
__global__ void __launch_bounds__(256, 2)
gemm_kernel(const float* __restrict__ A, const float* __restrict__ x, int N) {
    extern __shared__ char ring[];      // RING * STAGE_BYTES
    __shared__ float wred[8][16];

    int tid = threadIdx.x, w = tid >> 5, lane = tid & 31;
    int g = lane >> 2, t = lane & 3;
    int tile  = blockIdx.x >> 2;        // 0..624
    int kpart = blockIdx.x & 3;         // 0..3
    int row0 = tile * 16;
    int sgbase = kpart * STAGES_PER_CTA;

    uint32_t sb = smem_u32(ring);
    // loader mapping: col16 fixed per thread; 4 rows per thread
    int col16 = tid & 63;
    int rbase = tid >> 6;               // 0..3 ; rows = rbase + 4q

    float c[8][4];
#pragma unroll
    for (int j = 0; j < 8; j++)
#pragma unroll
        for (int q = 0; q < 4; q++) c[j][q] = 0.0f;

    // ---- prologue: load stages 0..RING-2 ----
#pragma unroll
    for (int ls = 0; ls < RING - 1; ls++) {
        int sg = sgbase + ls;
        int gk = sg * 256 + col16 * 4;      // global k float index
        if (gk < N) {
            uint32_t dbase = sb + (uint32_t)(ls & (RING - 1)) * STAGE_BYTES + col16 * 16;
#pragma unroll
            for (int q = 0; q < 4; q++) {
                int row = rbase + 4 * q;
                cp_async16(dbase + row * ROWSTRIDE,
                           A + (size_t)(row0 + row) * N + gk);
            }
        }
        CP_COMMIT();
    }

    const uint4* pB = g_Bp + lane;

    for (int ls = 0; ls < STAGES_PER_CTA; ls++) {
        int sg = sgbase + ls;
        int buf = ls & (RING - 1);

        CP_WAIT2();          // stage ls data arrived
        __syncthreads();

        // B fragments for this warp's two K-steps (global ks; >=625 reads zeros)
        int ks0 = sg * 16 + 2 * w;
        uint4 b0[4], b1[4];
#pragma unroll
        for (int jj = 0; jj < 4; jj++) {
            b0[jj] = pB[(size_t)(ks0 * 4 + jj) * 32];
            b1[jj] = pB[(size_t)((ks0 + 1) * 4 + jj) * 32];
        }

        // A fragments from smem (conflict-free LDS.128)
        uint32_t abase = sb + (uint32_t)buf * STAGE_BYTES + g * ROWSTRIDE
                       + (2 * w) * 64 + t * 16;
        float4 va0, vb0, va1, vb1;
        lds128(va0, abase);
        lds128(vb0, abase + 8 * ROWSTRIDE);
        lds128(va1, abase + 64);
        lds128(vb1, abase + 64 + 8 * ROWSTRIDE);

        uint32_t ar0[4], ar1[4];
        ar0[0] = cvt_bf16x2(va0.x, va0.y);
        ar0[1] = cvt_bf16x2(vb0.x, vb0.y);
        ar0[2] = cvt_bf16x2(va0.z, va0.w);
        ar0[3] = cvt_bf16x2(vb0.z, vb0.w);
        ar1[0] = cvt_bf16x2(va1.x, va1.y);
        ar1[1] = cvt_bf16x2(vb1.x, vb1.y);
        ar1[2] = cvt_bf16x2(va1.z, va1.w);
        ar1[3] = cvt_bf16x2(vb1.z, vb1.w);

#pragma unroll
        for (int jj = 0; jj < 4; jj++) {
            mma16816(c[2 * jj],     ar0, b0[jj].x, b0[jj].y);
            mma16816(c[2 * jj + 1], ar0, b0[jj].z, b0[jj].w);
            mma16816(c[2 * jj],     ar1, b1[jj].x, b1[jj].y);
            mma16816(c[2 * jj + 1], ar1, b1[jj].z, b1[jj].w);
        }

        // issue loads for stage ls + RING - 1 (buffer freed at iter ls-1)
        int lsn = ls + RING - 1;
        if (lsn < STAGES_PER_CTA) {
            int sgn = sgbase + lsn;
            int gk = sgn * 256 + col16 * 4;
            if (gk < N) {
                uint32_t dbase = sb + (uint32_t)(lsn & (RING - 1)) * STAGE_BYTES + col16 * 16;
#pragma unroll
                for (int q = 0; q < 4; q++) {
                    int row = rbase + 4 * q;
                    cp_async16(dbase + row * ROWSTRIDE,
                               A + (size_t)(row0 + row) * N + gk);
                }
            }
        }
        CP_COMMIT();   // always commit to keep group counting uniform
    }

    // ---- epilogue: per-warp partial dot x . (Ax)_partial ----
    int r0 = row0 + g, r1 = r0 + 8;
    float s0 = 0.0f, s1 = 0.0f;
#pragma unroll
    for (int j = 0; j < 8; j++) {
        int col = j * 8 + t * 2;
        float2 x0 = *(const float2*)(x + (size_t)r0 * DIMV + col);
        float2 x1 = *(const float2*)(x + (size_t)r1 * DIMV + col);
        s0 += x0.x * c[j][0] + x0.y * c[j][1];
        s1 += x1.x * c[j][2] + x1.y * c[j][3];
    }
    s0 += __shfl_xor_sync(0xFFFFFFFFu, s0, 1);
    s0 += __shfl_xor_sync(0xFFFFFFFFu, s0, 2);
    s1 += __shfl_xor_sync(0xFFFFFFFFu, s1, 1);
    s1 += __shfl_xor_sync(0xFFFFFFFFu, s1, 2);

    if (t == 0) { wred[w][g] = s0; wred[w][g + 8] = s1; }
    __syncthreads();

    if (tid < 16) {
        float acc = 0.0f;
#pragma unroll
        for (int q = 0; q < 8; q++) acc += wred[q][tid];
        atomicAdd(&g_w[row0 + tid], acc);
    }
}

// ---------------- kernel 3: elementwise finish ----------------
__global__ void __launch_bounds__(256) final_kernel(const float* __restrict__ x,
                                                    float* __restrict__ out) {
    int i = blockIdx.x * 256 + threadIdx.x;   // one float4 per thread
    int r = i >> 4, cq = i & 15;
    float inter = 0.01f * g_w[r];
    float4 xv = *(const float4*)(x + (size_t)r * DIMV + cq * 4);
    float4 o;
    o.x = 1.0f - 0.1f * xv.x - inter;
    o.y = 1.0f - 0.1f * xv.y - inter;
    o.z = 1.0f - 0.1f * xv.z - inter;
    o.w = 1.0f - 0.1f * xv.w - inter;
    *(float4*)(out + (size_t)r * DIMV + cq * 4) = o;
}

// ---------------- launch ----------------
extern "C" void kernel_launch(void* const* d_in, const int* in_sizes, int n_in,
                              void* d_out, int out_size) {
    const float* x = (const float*)d_in[1];
    const float* A = (const float*)d_in[2];
    float* out = (float*)d_out;
    int N = in_sizes[1] / DIMV;   // 10000
    int nk = N >> 4;              // 625

    void* wptr = nullptr;
    cudaGetSymbolAddress(&wptr, g_w);
    cudaMemsetAsync(wptr, 0, sizeof(float) * 10240);

    pack_kernel<<<nk, 128>>>(x, N);

    cudaFuncSetAttribute(gemm_kernel, cudaFuncAttributeMaxDynamicSharedMemorySize,
                         RING * STAGE_BYTES);
    gemm_kernel<<<(N / 16) * KSPLIT, 256, RING * STAGE_BYTES>>>(A, x, N);

    final_kernel<<<(N * DIMV) / (256 * 4), 256>>>(x, out);
}